// round 16
// baseline (speedup 1.0000x reference)
#include <cuda_runtime.h>
#include <cuda_bf16.h>
#include <math.h>
#include <stdint.h>

#define S_LEN  2048
#define HID    3584
#define NHEADS 28
#define NKV    4
#define HDIM   128
#define KVDIM  512
#define GROUPS 7
#define QKVW   (HID + 2 * KVDIM)   // 4608
#define ROPE_COLS (HID + KVDIM)
#define HSPLIT 5                   // y-tiles [0,5) -> HMMA, [5,16) -> FMA2

typedef unsigned long long ull;

// ---------------- scratch (allocation-free) ----------------
__device__ float g_QKV[S_LEN * QKVW];
__device__ float g_AO [S_LEN * HID];
__device__ float g_cs [S_LEN * 64];
__device__ float g_sn [S_LEN * 64];
__device__ float g_bqkv[QKVW];
__device__ float g_Wc [ (size_t)QKVW * HID ];
__device__ __nv_bfloat16 g_AOh[S_LEN * HID];
__device__ __nv_bfloat16 g_AOl[S_LEN * HID];
__device__ __nv_bfloat16 g_Woh[(size_t)HID * HID];
__device__ __nv_bfloat16 g_Wol[(size_t)HID * HID];

// ============================================================
// helpers
// ============================================================
__device__ __forceinline__ ull dup2(float x) {
    ull r; asm("mov.b64 %0, {%1, %1};" : "=l"(r) : "f"(x)); return r;
}
__device__ __forceinline__ void fma2(ull& d, ull a, ull b) {
    asm("fma.rn.f32x2 %0, %1, %2, %0;" : "+l"(d) : "l"(a), "l"(b));
}
__device__ __forceinline__ void mul2(ull& d, ull a) {
    asm("mul.rn.f32x2 %0, %0, %1;" : "+l"(d) : "l"(a));
}
__device__ __forceinline__ float2 up2(ull v) {
    float2 f; asm("mov.b64 {%0, %1}, %2;" : "=f"(f.x), "=f"(f.y) : "l"(v)); return f;
}
__device__ __forceinline__ uint32_t smem_u32(const void* p) {
    uint32_t a;
    asm("{ .reg .u64 t; cvta.to.shared.u64 t, %1; cvt.u32.u64 %0, t; }"
        : "=r"(a) : "l"(p));
    return a;
}
__device__ __forceinline__ void ldsm_x4(uint32_t addr, uint32_t* r) {
    asm volatile("ldmatrix.sync.aligned.m8n8.x4.shared.b16 {%0,%1,%2,%3}, [%4];"
                 : "=r"(r[0]), "=r"(r[1]), "=r"(r[2]), "=r"(r[3]) : "r"(addr));
}
__device__ __forceinline__ void mma_bf16(float* c, const uint32_t* a,
                                         const uint32_t* b) {
    asm volatile("mma.sync.aligned.m16n8k16.row.col.f32.bf16.bf16.f32 "
                 "{%0,%1,%2,%3}, {%4,%5,%6,%7}, {%8,%9}, {%0,%1,%2,%3};"
                 : "+f"(c[0]), "+f"(c[1]), "+f"(c[2]), "+f"(c[3])
                 : "r"(a[0]), "r"(a[1]), "r"(a[2]), "r"(a[3]),
                   "r"(b[0]), "r"(b[1]));
}
#define CP_ASYNC16(dst, src) \
    asm volatile("cp.async.cg.shared.global [%0], [%1], 16;" \
                 :: "r"(dst), "l"(src) : "memory")
#define CP_COMMIT() asm volatile("cp.async.commit_group;" ::: "memory")
#define CP_WAIT0()  asm volatile("cp.async.wait_group 0;" ::: "memory")

// ============================================================
// fp32 -> bf16 hi/lo split
// ============================================================
__global__ void cvt_split(const float* __restrict__ src,
                          __nv_bfloat16* __restrict__ hi,
                          __nv_bfloat16* __restrict__ lo, int n4)
{
    int i = blockIdx.x * blockDim.x + threadIdx.x;
    if (i >= n4) return;
    float4 v = ((const float4*)src)[i];
    __nv_bfloat16 h0 = __float2bfloat16(v.x);
    __nv_bfloat16 h1 = __float2bfloat16(v.y);
    __nv_bfloat16 h2 = __float2bfloat16(v.z);
    __nv_bfloat16 h3 = __float2bfloat16(v.w);
    __nv_bfloat162 hh0 = {h0, h1}, hh1 = {h2, h3};
    __nv_bfloat162 ll0, ll1;
    ll0.x = __float2bfloat16(v.x - __bfloat162float(h0));
    ll0.y = __float2bfloat16(v.y - __bfloat162float(h1));
    ll1.x = __float2bfloat16(v.z - __bfloat162float(h2));
    ll1.y = __float2bfloat16(v.w - __bfloat162float(h3));
    ((__nv_bfloat162*)hi)[i * 2]     = hh0;
    ((__nv_bfloat162*)hi)[i * 2 + 1] = hh1;
    ((__nv_bfloat162*)lo)[i * 2]     = ll0;
    ((__nv_bfloat162*)lo)[i * 2 + 1] = ll1;
}

// ============================================================
// f32x2 SGEMM (QKV): C = A @ B^T + bias, RoPE fused epilogue.
// CTA 128x128, BK=16, 256 thr, 8x8/thread, 2 CTAs/SM, 1 barrier/kb.
// ============================================================
#define KSTR  132
#define TBUFF (16 * KSTR)
#define G2_SMEM (4 * TBUFF * 4)          // 33792 B

__global__ void __launch_bounds__(256, 2)
gemm2(const float* __restrict__ A, const float* __restrict__ B,
      const float* __restrict__ bias, float* __restrict__ C,
      int N, int K, int rope_cols)
{
    extern __shared__ char smem[];
    float* Asf = (float*)smem;
    float* Bsf = (float*)smem + 2 * TBUFF;

    const int tid = threadIdx.x;
    const int tx  = tid & 15;
    const int ty  = tid >> 4;
    const int m0  = blockIdx.y * 128;
    const int n0  = blockIdx.x * 128;
    const int r0  = tid >> 2;
    const int c4  = tid & 3;
    const int nkb = K / 16;

    float4 pa[2], pb[2];
#pragma unroll
    for (int jj = 0; jj < 2; jj++) {
        int row = r0 + 64 * jj;
        pa[jj] = *(const float4*)(A + (size_t)(m0 + row) * K + c4 * 4);
        pb[jj] = *(const float4*)(B + (size_t)(n0 + row) * K + c4 * 4);
    }
    {
        float av4[2][4] = {{pa[0].x, pa[0].y, pa[0].z, pa[0].w},
                           {pa[1].x, pa[1].y, pa[1].z, pa[1].w}};
        float bv4[2][4] = {{pb[0].x, pb[0].y, pb[0].z, pb[0].w},
                           {pb[1].x, pb[1].y, pb[1].z, pb[1].w}};
#pragma unroll
        for (int jj = 0; jj < 2; jj++) {
            int row = r0 + 64 * jj;
#pragma unroll
            for (int kk = 0; kk < 4; kk++) {
                Asf[(c4 * 4 + kk) * KSTR + row] = av4[jj][kk];
                Bsf[(c4 * 4 + kk) * KSTR + row] = bv4[jj][kk];
            }
        }
    }
    __syncthreads();

    ull acc[8][4];
#pragma unroll
    for (int i = 0; i < 8; i++)
#pragma unroll
        for (int j = 0; j < 4; j++) acc[i][j] = 0ULL;

    for (int kb = 0; kb < nkb; kb++) {
        if (kb + 1 < nkb) {
#pragma unroll
            for (int jj = 0; jj < 2; jj++) {
                int row = r0 + 64 * jj;
                pa[jj] = *(const float4*)(A + (size_t)(m0 + row) * K +
                                          (kb + 1) * 16 + c4 * 4);
                pb[jj] = *(const float4*)(B + (size_t)(n0 + row) * K +
                                          (kb + 1) * 16 + c4 * 4);
            }
        }
        const float* As = Asf + (kb & 1) * TBUFF;
        const float* Bs = Bsf + (kb & 1) * TBUFF;
#pragma unroll
        for (int k = 0; k < 16; k++) {
            const float* ar = As + k * KSTR;
            const float* br = Bs + k * KSTR;
            float4 af0 = *(const float4*)(ar + 4 * ty);
            float4 af1 = *(const float4*)(ar + 64 + 4 * ty);
            ulonglong2 b0 = *(const ulonglong2*)(br + 4 * tx);
            ulonglong2 b1 = *(const ulonglong2*)(br + 64 + 4 * tx);
            ull av[8];
            av[0] = dup2(af0.x); av[1] = dup2(af0.y);
            av[2] = dup2(af0.z); av[3] = dup2(af0.w);
            av[4] = dup2(af1.x); av[5] = dup2(af1.y);
            av[6] = dup2(af1.z); av[7] = dup2(af1.w);
            ull bv[4] = {b0.x, b0.y, b1.x, b1.y};
#pragma unroll
            for (int i = 0; i < 8; i++)
#pragma unroll
                for (int j = 0; j < 4; j++)
                    fma2(acc[i][j], av[i], bv[j]);
        }
        if (kb + 1 < nkb) {
            int buf = (kb + 1) & 1;
            float av4[2][4] = {{pa[0].x, pa[0].y, pa[0].z, pa[0].w},
                               {pa[1].x, pa[1].y, pa[1].z, pa[1].w}};
            float bv4[2][4] = {{pb[0].x, pb[0].y, pb[0].z, pb[0].w},
                               {pb[1].x, pb[1].y, pb[1].z, pb[1].w}};
#pragma unroll
            for (int jj = 0; jj < 2; jj++) {
                int row = r0 + 64 * jj;
#pragma unroll
                for (int kk = 0; kk < 4; kk++) {
                    Asf[buf * TBUFF + (c4 * 4 + kk) * KSTR + row] = av4[jj][kk];
                    Bsf[buf * TBUFF + (c4 * 4 + kk) * KSTR + row] = bv4[jj][kk];
                }
            }
        }
        __syncthreads();
    }

    float bb[8];
#pragma unroll
    for (int q = 0; q < 8; q++) {
        int n = n0 + (q < 4 ? 4 * tx + q : 64 + 4 * tx + (q - 4));
        bb[q] = bias ? bias[n] : 0.0f;
    }
    const bool do_rope = (n0 < rope_cols);

#pragma unroll
    for (int i = 0; i < 8; i++) {
        int m = m0 + (i < 4 ? 4 * ty + i : 64 + 4 * ty + (i - 4));
        float* crow = C + (size_t)m * N + n0;
        float2 p0 = up2(acc[i][0]);
        float2 p1 = up2(acc[i][1]);
        float2 p2 = up2(acc[i][2]);
        float2 p3 = up2(acc[i][3]);
        float4 o0 = {p0.x + bb[0], p0.y + bb[1], p1.x + bb[2], p1.y + bb[3]};
        float4 o1 = {p2.x + bb[4], p2.y + bb[5], p3.x + bb[6], p3.y + bb[7]};
        if (do_rope) {
            float4 cs = *(const float4*)(g_cs + (size_t)m * 64 + 4 * tx);
            float4 sn = *(const float4*)(g_sn + (size_t)m * 64 + 4 * tx);
            float4 t0 = o0;
            o0.x = t0.x * cs.x - o1.x * sn.x;
            o0.y = t0.y * cs.y - o1.y * sn.y;
            o0.z = t0.z * cs.z - o1.z * sn.z;
            o0.w = t0.w * cs.w - o1.w * sn.w;
            o1.x = o1.x * cs.x + t0.x * sn.x;
            o1.y = o1.y * cs.y + t0.y * sn.y;
            o1.z = o1.z * cs.z + t0.z * sn.z;
            o1.w = o1.w * cs.w + t0.w * sn.w;
        }
        *(float4*)(crow + 4 * tx)      = o0;
        *(float4*)(crow + 64 + 4 * tx) = o1;
    }
}

// ============================================================
// HYBRID O-projection: out[2048,3584] = AO @ Wo^T
// blockIdx.y < HSPLIT  -> HMMA path (bf16 3-pass, tensor pipe)
// blockIdx.y >= HSPLIT -> FMA2 path (fp32, fma pipe)
// 256 threads, 64KB SMEM, 2 CTAs/SM.
// ============================================================
#define HT_TILE 16384                 // one 128x64 bf16 tile
#define OG_SMEM (4 * HT_TILE)         // 65536 B (single-buffer HMMA; FMA2 uses 33792)

__global__ void __launch_bounds__(256, 2)
ogemm(const float* __restrict__ A, const float* __restrict__ B,
      float* __restrict__ C)
{
    extern __shared__ char smem[];
    const int tid = threadIdx.x;
    const int n0  = blockIdx.x * 128;

    if (blockIdx.y < HSPLIT) {
        // ================= HMMA path =================
        const uint32_t sb = smem_u32(smem);
        const int lane   = tid & 31;
        const int wid    = tid >> 5;
        const int warp_m = wid & 3;
        const int warp_n = wid >> 2;
        const int m0 = blockIdx.y * 128;

        const __nv_bfloat16* gsrc[4] = {
            g_AOh + (size_t)m0 * HID, g_AOl + (size_t)m0 * HID,
            g_Woh + (size_t)n0 * HID, g_Wol + (size_t)n0 * HID };

        const int lr = tid >> 3;      // 0..31
        const int lc = tid & 7;       // chunk

        float c[2][8][4];
#pragma unroll
        for (int i = 0; i < 2; i++)
#pragma unroll
            for (int j = 0; j < 8; j++)
#pragma unroll
                for (int z = 0; z < 4; z++) c[i][j][z] = 0.0f;

        const int a_row  = warp_m * 32 + (lane & 15);
        const int a_csel = lane >> 4;
        const int b_row  = warp_n * 64 + (lane & 7) + ((lane >> 4) << 3);
        const int b_csel = (lane >> 3) & 1;

        for (int kb = 0; kb < HID / 64; kb++) {
            // load all 4 tiles (single buffer)
#pragma unroll
            for (int arr = 0; arr < 4; arr++) {
#pragma unroll
                for (int j = 0; j < 4; j++) {
                    int row = lr + 32 * j;
                    const __nv_bfloat16* src =
                        gsrc[arr] + (size_t)row * HID + kb * 64 + lc * 8;
                    uint32_t dst = sb + arr * HT_TILE + row * 128 +
                                   ((lc ^ (row & 7)) << 4);
                    CP_ASYNC16(dst, src);
                }
            }
            CP_COMMIT(); CP_WAIT0();
            __syncthreads();

            const uint32_t tAh = sb;
            const uint32_t tAl = sb + HT_TILE;
            const uint32_t tBh = sb + 2 * HT_TILE;
            const uint32_t tBl = sb + 3 * HT_TILE;

#pragma unroll
            for (int ks = 0; ks < 4; ks++) {
                const int kc = ks * 2;
                uint32_t ah[2][4], al[2][4];
#pragma unroll
                for (int mt = 0; mt < 2; mt++) {
                    int row   = a_row + mt * 16;
                    int chunk = kc + a_csel;
                    uint32_t off = row * 128 + ((chunk ^ (row & 7)) << 4);
                    ldsm_x4(tAh + off, ah[mt]);
                    ldsm_x4(tAl + off, al[mt]);
                }
#pragma unroll
                for (int np = 0; np < 4; np++) {
                    int row   = b_row + np * 16;
                    int chunk = kc + b_csel;
                    uint32_t off = row * 128 + ((chunk ^ (row & 7)) << 4);
                    uint32_t bh4[4], bl4[4];
                    ldsm_x4(tBh + off, bh4);
                    ldsm_x4(tBl + off, bl4);
#pragma unroll
                    for (int mt = 0; mt < 2; mt++) {
#pragma unroll
                        for (int hf = 0; hf < 2; hf++) {
                            uint32_t* bhp = &bh4[hf * 2];
                            uint32_t* blp = &bl4[hf * 2];
                            float* cc = c[mt][np * 2 + hf];
                            mma_bf16(cc, ah[mt], bhp);
                            mma_bf16(cc, ah[mt], blp);
                            mma_bf16(cc, al[mt], bhp);
                        }
                    }
                }
            }
            __syncthreads();
        }

        // epilogue (no bias)
#pragma unroll
        for (int mt = 0; mt < 2; mt++) {
#pragma unroll
            for (int nt = 0; nt < 8; nt++) {
                int m = m0 + warp_m * 32 + mt * 16 + (lane >> 2);
                int n = n0 + warp_n * 64 + nt * 8 + (lane & 3) * 2;
                float2 v0 = {c[mt][nt][0], c[mt][nt][1]};
                float2 v1 = {c[mt][nt][2], c[mt][nt][3]};
                *(float2*)(C + (size_t)m * HID + n)       = v0;
                *(float2*)(C + (size_t)(m + 8) * HID + n) = v1;
            }
        }
    } else {
        // ================= FMA2 path =================
        float* Asf = (float*)smem;
        float* Bsf = (float*)smem + 2 * TBUFF;

        const int tx  = tid & 15;
        const int ty  = tid >> 4;
        const int m0  = blockIdx.y * 128;
        const int r0  = tid >> 2;
        const int c4  = tid & 3;
        const int nkb = HID / 16;

        float4 pa[2], pb[2];
#pragma unroll
        for (int jj = 0; jj < 2; jj++) {
            int row = r0 + 64 * jj;
            pa[jj] = *(const float4*)(A + (size_t)(m0 + row) * HID + c4 * 4);
            pb[jj] = *(const float4*)(B + (size_t)(n0 + row) * HID + c4 * 4);
        }
        {
            float av4[2][4] = {{pa[0].x, pa[0].y, pa[0].z, pa[0].w},
                               {pa[1].x, pa[1].y, pa[1].z, pa[1].w}};
            float bv4[2][4] = {{pb[0].x, pb[0].y, pb[0].z, pb[0].w},
                               {pb[1].x, pb[1].y, pb[1].z, pb[1].w}};
#pragma unroll
            for (int jj = 0; jj < 2; jj++) {
                int row = r0 + 64 * jj;
#pragma unroll
                for (int kk = 0; kk < 4; kk++) {
                    Asf[(c4 * 4 + kk) * KSTR + row] = av4[jj][kk];
                    Bsf[(c4 * 4 + kk) * KSTR + row] = bv4[jj][kk];
                }
            }
        }
        __syncthreads();

        ull acc[8][4];
#pragma unroll
        for (int i = 0; i < 8; i++)
#pragma unroll
            for (int j = 0; j < 4; j++) acc[i][j] = 0ULL;

        for (int kb = 0; kb < nkb; kb++) {
            if (kb + 1 < nkb) {
#pragma unroll
                for (int jj = 0; jj < 2; jj++) {
                    int row = r0 + 64 * jj;
                    pa[jj] = *(const float4*)(A + (size_t)(m0 + row) * HID +
                                              (kb + 1) * 16 + c4 * 4);
                    pb[jj] = *(const float4*)(B + (size_t)(n0 + row) * HID +
                                              (kb + 1) * 16 + c4 * 4);
                }
            }
            const float* As = Asf + (kb & 1) * TBUFF;
            const float* Bs = Bsf + (kb & 1) * TBUFF;
#pragma unroll
            for (int k = 0; k < 16; k++) {
                const float* ar = As + k * KSTR;
                const float* br = Bs + k * KSTR;
                float4 af0 = *(const float4*)(ar + 4 * ty);
                float4 af1 = *(const float4*)(ar + 64 + 4 * ty);
                ulonglong2 b0 = *(const ulonglong2*)(br + 4 * tx);
                ulonglong2 b1 = *(const ulonglong2*)(br + 64 + 4 * tx);
                ull av[8];
                av[0] = dup2(af0.x); av[1] = dup2(af0.y);
                av[2] = dup2(af0.z); av[3] = dup2(af0.w);
                av[4] = dup2(af1.x); av[5] = dup2(af1.y);
                av[6] = dup2(af1.z); av[7] = dup2(af1.w);
                ull bv[4] = {b0.x, b0.y, b1.x, b1.y};
#pragma unroll
                for (int i = 0; i < 8; i++)
#pragma unroll
                    for (int j = 0; j < 4; j++)
                        fma2(acc[i][j], av[i], bv[j]);
            }
            if (kb + 1 < nkb) {
                int buf = (kb + 1) & 1;
                float av4[2][4] = {{pa[0].x, pa[0].y, pa[0].z, pa[0].w},
                                   {pa[1].x, pa[1].y, pa[1].z, pa[1].w}};
                float bv4[2][4] = {{pb[0].x, pb[0].y, pb[0].z, pb[0].w},
                                   {pb[1].x, pb[1].y, pb[1].z, pb[1].w}};
#pragma unroll
                for (int jj = 0; jj < 2; jj++) {
                    int row = r0 + 64 * jj;
#pragma unroll
                    for (int kk = 0; kk < 4; kk++) {
                        Asf[buf * TBUFF + (c4 * 4 + kk) * KSTR + row] = av4[jj][kk];
                        Bsf[buf * TBUFF + (c4 * 4 + kk) * KSTR + row] = bv4[jj][kk];
                    }
                }
            }
            __syncthreads();
        }

#pragma unroll
        for (int i = 0; i < 8; i++) {
            int m = m0 + (i < 4 ? 4 * ty + i : 64 + 4 * ty + (i - 4));
            float* crow = C + (size_t)m * HID + n0;
            float2 p0 = up2(acc[i][0]);
            float2 p1 = up2(acc[i][1]);
            float2 p2 = up2(acc[i][2]);
            float2 p3 = up2(acc[i][3]);
            float4 o0 = {p0.x, p0.y, p1.x, p1.y};
            float4 o1 = {p2.x, p2.y, p3.x, p3.y};
            *(float4*)(crow + 4 * tx)      = o0;
            *(float4*)(crow + 64 + 4 * tx) = o1;
        }
    }
}

// ============================================================
// weight pack + bias pack + RoPE table
// ============================================================
__global__ void wpack(const float* __restrict__ Wq,
                      const float* __restrict__ Wk,
                      const float* __restrict__ Wv)
{
    int i = blockIdx.x * blockDim.x + threadIdx.x;
    const int rowq = HID / 4;
    if (i >= QKVW * rowq) return;
    int n = i / rowq;
    int c = i - n * rowq;
    float4 v;
    if (n < HID)              v = ((const float4*)Wq)[(size_t)n * rowq + c];
    else if (n < HID + KVDIM) v = ((const float4*)Wk)[(size_t)(n - HID) * rowq + c];
    else                      v = ((const float4*)Wv)[(size_t)(n - HID - KVDIM) * rowq + c];
    ((float4*)g_Wc)[i] = v;
}

__global__ void bias_pack(const float* __restrict__ bq,
                          const float* __restrict__ bk,
                          const float* __restrict__ bv)
{
    int i = blockIdx.x * blockDim.x + threadIdx.x;
    if (i >= QKVW) return;
    float v;
    if (i < HID)              v = bq[i];
    else if (i < HID + KVDIM) v = bk[i - HID];
    else                      v = bv[i - HID - KVDIM];
    g_bqkv[i] = v;
}

__global__ void rope_table(const int* __restrict__ pos_ids)
{
    const int s = blockIdx.x;
    const int i = threadIdx.x;
    double inv = pow(10000.0, -(double)i / 64.0);
    double ang = (double)pos_ids[s] * inv;
    g_cs[s * 64 + i] = (float)cos(ang);
    g_sn[s * 64 + i] = (float)sin(ang);
}

// ============================================================
// Causal GQA flash-attention (R15 version)
// ============================================================
#define ATTN_SMEM_FLOATS (64*128 + 128*64 + 64*128 + 64*65 + 192)
#define ATTN_SMEM_BYTES  (ATTN_SMEM_FLOATS * 4)

__global__ void __launch_bounds__(256)
attn_kernel()
{
    extern __shared__ float sm[];
    float* Qs   = sm;
    float* Kst  = Qs  + 64 * 128;
    float* Vs   = Kst + 128 * 64;
    float* Ss   = Vs  + 64 * 128;
    float* mrow = Ss  + 64 * 65;
    float* lrow = mrow + 64;
    float* arow = lrow + 64;

    const int qt  = gridDim.x - 1 - blockIdx.x;
    const int h   = blockIdx.y;
    const int kvh = h / GROUPS;
    const int tid = threadIdx.x;
    const int qm  = qt * 64;
    const float scale = 0.08838834764831845f;

#pragma unroll
    for (int t = 0; t < 8; t++) {
        int idx = tid + 256 * t;
        int r   = idx >> 5;
        int c4  = idx & 31;
        float4 v = *(const float4*)(g_QKV + (size_t)(qm + r) * QKVW + h * HDIM + c4 * 4);
        v.x *= scale; v.y *= scale; v.z *= scale; v.w *= scale;
        *(float4*)(Qs + r * 128 + c4 * 4) = v;
    }

    ull acc2[16];
#pragma unroll
    for (int z = 0; z < 16; z++) acc2[z] = 0ULL;
    const int ocg  = tid >> 6;
    const int orow = tid & 63;

    if (tid < 64) { mrow[tid] = -1e30f; lrow[tid] = 0.0f; }
    __syncthreads();

    const int sx = tid & 15;
    const int sy = tid >> 4;
    const int ntiles = qt + 1;

    for (int kt = 0; kt < ntiles; kt++) {
        const int kn = kt * 64;
#pragma unroll
        for (int t = 0; t < 8; t++) {
            int idx = tid + 256 * t;
            int d4  = idx >> 6;
            int n   = idx & 63;
            float4 v = *(const float4*)(g_QKV + (size_t)(kn + n) * QKVW +
                                        HID + kvh * HDIM + d4 * 4);
            Kst[(d4 * 4 + 0) * 64 + n] = v.x;
            Kst[(d4 * 4 + 1) * 64 + n] = v.y;
            Kst[(d4 * 4 + 2) * 64 + n] = v.z;
            Kst[(d4 * 4 + 3) * 64 + n] = v.w;
        }
#pragma unroll
        for (int t = 0; t < 8; t++) {
            int idx = tid + 256 * t;
            int r   = idx >> 5;
            int c4  = idx & 31;
            *(float4*)(Vs + r * 128 + c4 * 4) =
                *(const float4*)(g_QKV + (size_t)(kn + r) * QKVW +
                                 HID + KVDIM + kvh * HDIM + c4 * 4);
        }
        __syncthreads();

        ull sacc2[4][2];
#pragma unroll
        for (int i = 0; i < 4; i++) { sacc2[i][0] = 0ULL; sacc2[i][1] = 0ULL; }

#pragma unroll 8
        for (int d = 0; d < 128; d += 4) {
            float4 av[4];
#pragma unroll
            for (int i = 0; i < 4; i++)
                av[i] = *(const float4*)(Qs + (sy * 4 + i) * 128 + d);
            ulonglong2 bp[4];
#pragma unroll
            for (int e = 0; e < 4; e++)
                bp[e] = *(const ulonglong2*)(Kst + (d + e) * 64 + sx * 4);
#pragma unroll
            for (int i = 0; i < 4; i++) {
                float ae[4] = {av[i].x, av[i].y, av[i].z, av[i].w};
#pragma unroll
                for (int e = 0; e < 4; e++) {
                    ull ad = dup2(ae[e]);
                    fma2(sacc2[i][0], ad, bp[e].x);
                    fma2(sacc2[i][1], ad, bp[e].y);
                }
            }
        }

        const bool diag = (kt == qt);
#pragma unroll
        for (int i = 0; i < 4; i++) {
            int qr = sy * 4 + i;
            float2 s0 = up2(sacc2[i][0]);
            float2 s1 = up2(sacc2[i][1]);
            float vj[4] = {s0.x, s0.y, s1.x, s1.y};
#pragma unroll
            for (int j = 0; j < 4; j++) {
                int kc = sx * 4 + j;
                float v = vj[j];
                if (diag && kc > qr) v = -1e30f;
                Ss[qr * 65 + kc] = v;
            }
        }
        __syncthreads();

        {
            int r   = tid >> 2;
            int seg = tid & 3;
            float* sr = Ss + r * 65 + seg * 16;
            float mx = -1e30f;
#pragma unroll
            for (int k = 0; k < 16; k++) mx = fmaxf(mx, sr[k]);
            mx = fmaxf(mx, __shfl_xor_sync(0xffffffffu, mx, 1));
            mx = fmaxf(mx, __shfl_xor_sync(0xffffffffu, mx, 2));
            float m_old = mrow[r];
            float mnew  = fmaxf(m_old, mx);
            float sum = 0.0f;
#pragma unroll
            for (int k = 0; k < 16; k++) {
                float p = __expf(sr[k] - mnew);
                sr[k] = p;
                sum += p;
            }
            sum += __shfl_xor_sync(0xffffffffu, sum, 1);
            sum += __shfl_xor_sync(0xffffffffu, sum, 2);
            if (seg == 0) {
                float a = __expf(m_old - mnew);
                lrow[r] = lrow[r] * a + sum;
                mrow[r] = mnew;
                arow[r] = a;
            }
        }
        __syncthreads();

        {
            ull aa = dup2(arow[orow]);
#pragma unroll
            for (int z = 0; z < 16; z++) mul2(acc2[z], aa);
        }
        const float* srow = Ss + orow * 65;
#pragma unroll 4
        for (int kk = 0; kk < 64; kk++) {
            ull pp = dup2(srow[kk]);
            const float* vrow = Vs + kk * 128 + ocg * 32;
#pragma unroll
            for (int j = 0; j < 8; j++) {
                ulonglong2 v = *(const ulonglong2*)(vrow + j * 4);
                fma2(acc2[2 * j],     pp, v.x);
                fma2(acc2[2 * j + 1], pp, v.y);
            }
        }
        __syncthreads();
    }

    const float inv_l = 1.0f / lrow[orow];
    float* op = g_AO + (size_t)(qm + orow) * HID + h * HDIM + ocg * 32;
#pragma unroll
    for (int j = 0; j < 8; j++) {
        float2 e0 = up2(acc2[2 * j]);
        float2 e1 = up2(acc2[2 * j + 1]);
        float4 o = {e0.x * inv_l, e0.y * inv_l, e1.x * inv_l, e1.y * inv_l};
        *(float4*)(op + j * 4) = o;
    }
}

// ============================================================
// launch
// ============================================================
extern "C" void kernel_launch(void* const* d_in, const int* in_sizes, int n_in,
                              void* d_out, int out_size)
{
    const float* hs  = (const float*)d_in[0];
    const int*   pos = (const int*)  d_in[1];
    const float* Wq  = (const float*)d_in[2];
    const float* bq  = (const float*)d_in[3];
    const float* Wk  = (const float*)d_in[4];
    const float* bk  = (const float*)d_in[5];
    const float* Wv  = (const float*)d_in[6];
    const float* bv  = (const float*)d_in[7];
    const float* Wo  = (const float*)d_in[8];
    float* out = (float*)d_out;

    void *qkvp, *aop, *bqkv, *wc, *aoh, *aol, *woh, *wol;
    cudaGetSymbolAddress(&qkvp, g_QKV);
    cudaGetSymbolAddress(&aop,  g_AO);
    cudaGetSymbolAddress(&bqkv, g_bqkv);
    cudaGetSymbolAddress(&wc,   g_Wc);
    cudaGetSymbolAddress(&aoh,  g_AOh);
    cudaGetSymbolAddress(&aol,  g_AOl);
    cudaGetSymbolAddress(&woh,  g_Woh);
    cudaGetSymbolAddress(&wol,  g_Wol);

    cudaFuncSetAttribute(attn_kernel,
                         cudaFuncAttributeMaxDynamicSharedMemorySize,
                         ATTN_SMEM_BYTES);
    cudaFuncSetAttribute(gemm2,
                         cudaFuncAttributeMaxDynamicSharedMemorySize,
                         G2_SMEM);
    cudaFuncSetAttribute(ogemm,
                         cudaFuncAttributeMaxDynamicSharedMemorySize,
                         OG_SMEM);

    int npack4 = QKVW * (HID / 4);
    wpack<<<(npack4 + 255) / 256, 256>>>(Wq, Wk, Wv);
    bias_pack<<<(QKVW + 255) / 256, 256>>>(bq, bk, bv);
    rope_table<<<S_LEN, 64>>>(pos);
    // Wo bf16 split (for the HMMA rows of the O projection)
    {
        int n4 = (HID * HID) / 4;
        cvt_split<<<(n4 + 255) / 256, 256>>>(Wo, (__nv_bfloat16*)woh,
                                             (__nv_bfloat16*)wol, n4);
    }

    // fused QKV projection + RoPE epilogue (pure FMA2)
    gemm2<<<dim3(QKVW / 128, S_LEN / 128, 1), 256, G2_SMEM>>>(
        hs, (const float*)wc, (const float*)bqkv, (float*)qkvp,
        QKVW, HID, ROPE_COLS);

    attn_kernel<<<dim3(S_LEN / 64, NHEADS), 256, ATTN_SMEM_BYTES>>>();

    // AO bf16 split, then hybrid O-projection (tensor + fma pipes)
    {
        int n4 = (S_LEN * HID) / 4;
        cvt_split<<<(n4 + 255) / 256, 256>>>((const float*)aop,
                                             (__nv_bfloat16*)aoh,
                                             (__nv_bfloat16*)aol, n4);
    }
    ogemm<<<dim3(HID / 128, S_LEN / 128), 256, OG_SMEM>>>(
        (const float*)aop, Wo, out);
}

// round 17
// speedup vs baseline: 1.0441x; 1.0441x over previous
#include <cuda_runtime.h>
#include <math.h>
#include <stdint.h>

#define S_LEN  2048
#define HID    3584
#define NHEADS 28
#define NKV    4
#define HDIM   128
#define KVDIM  512
#define GROUPS 7
#define QKVW   (HID + 2 * KVDIM)   // 4608
#define ROPE_COLS (HID + KVDIM)    // rope applies to cols [0, 4096)
#define SPLITK 7

typedef unsigned long long ull;

// ---------------- scratch (allocation-free) ----------------
__device__ float g_QKV[S_LEN * QKVW];
__device__ float g_AO [S_LEN * HID];
__device__ float g_cs [S_LEN * 64];
__device__ float g_sn [S_LEN * 64];
__device__ float g_P  [ (size_t)SPLITK * S_LEN * HID ];  // split-K partials

// ============================================================
// packed f32x2 helpers
// ============================================================
__device__ __forceinline__ ull dup2(float x) {
    ull r; asm("mov.b64 %0, {%1, %1};" : "=l"(r) : "f"(x)); return r;
}
__device__ __forceinline__ void fma2(ull& d, ull a, ull b) {
    asm("fma.rn.f32x2 %0, %1, %2, %0;" : "+l"(d) : "l"(a), "l"(b));
}
__device__ __forceinline__ void mul2(ull& d, ull a) {
    asm("mul.rn.f32x2 %0, %0, %1;" : "+l"(d) : "l"(a));
}
__device__ __forceinline__ float2 up2(ull v) {
    float2 f; asm("mov.b64 {%0, %1}, %2;" : "=f"(f.x), "=f"(f.y) : "l"(v)); return f;
}

// ============================================================
// f32x2 SGEMM: C[M,N] = A[M,K] @ B[N,K]^T + bias[N]
// B and bias chosen per n-block from 3 segments (kills wpack/bias_pack):
//   n0 < b1 -> (B0, bias0, n0); n0 < b2 -> (B1, bias1, n0-b1);
//   else    -> (B2, bias2, n0-b2)
// CTA 128x128, BK=16, 256 thr, 8x8/thread, double-buffered, 2 CTAs/SM,
// ONE barrier per k-block, RoPE fused in epilogue, split-K via gridDim.z.
// ============================================================
#define KSTR  132
#define TBUFF (16 * KSTR)
#define G2_SMEM (4 * TBUFF * 4)          // 33792 B

__global__ void __launch_bounds__(256, 2)
gemm2(const float* __restrict__ A,
      const float* __restrict__ B0, const float* __restrict__ B1,
      const float* __restrict__ B2,
      const float* __restrict__ bias0, const float* __restrict__ bias1,
      const float* __restrict__ bias2,
      float* __restrict__ C,
      int N, int K, int rope_cols, int b1, int b2)
{
    extern __shared__ char smem[];
    float* Asf = (float*)smem;
    float* Bsf = (float*)smem + 2 * TBUFF;

    const int tid = threadIdx.x;
    const int tx  = tid & 15;
    const int ty  = tid >> 4;
    const int m0  = blockIdx.y * 128;
    const int n0  = blockIdx.x * 128;
    const int r0  = tid >> 2;
    const int c4  = tid & 3;

    // segment select (uniform per block)
    const float* Bsel;  const float* bsel;  int nrel;
    if (n0 < b1)      { Bsel = B0; bsel = bias0; nrel = n0; }
    else if (n0 < b2) { Bsel = B1; bsel = bias1; nrel = n0 - b1; }
    else              { Bsel = B2; bsel = bias2; nrel = n0 - b2; }
    const float* Bbase = Bsel + (size_t)nrel * K;

    // split-K slice
    const int nkb_total = K / 16;
    const int per = (nkb_total + gridDim.z - 1) / gridDim.z;
    const int z   = blockIdx.z;
    const int kb0 = z * per;
    const int nkb = min(per, nkb_total - kb0);
    A     += (size_t)kb0 * 16;
    Bbase += (size_t)kb0 * 16;
    C     += (size_t)z * S_LEN * N;

    float4 pa[2], pb[2];

#pragma unroll
    for (int jj = 0; jj < 2; jj++) {
        int row = r0 + 64 * jj;
        pa[jj] = *(const float4*)(A + (size_t)(m0 + row) * K + c4 * 4);
        pb[jj] = *(const float4*)(Bbase + (size_t)row * K + c4 * 4);
    }
    {
        float av4[2][4] = {{pa[0].x, pa[0].y, pa[0].z, pa[0].w},
                           {pa[1].x, pa[1].y, pa[1].z, pa[1].w}};
        float bv4[2][4] = {{pb[0].x, pb[0].y, pb[0].z, pb[0].w},
                           {pb[1].x, pb[1].y, pb[1].z, pb[1].w}};
#pragma unroll
        for (int jj = 0; jj < 2; jj++) {
            int row = r0 + 64 * jj;
#pragma unroll
            for (int kk = 0; kk < 4; kk++) {
                Asf[(c4 * 4 + kk) * KSTR + row] = av4[jj][kk];
                Bsf[(c4 * 4 + kk) * KSTR + row] = bv4[jj][kk];
            }
        }
    }
    __syncthreads();

    ull acc[8][4];
#pragma unroll
    for (int i = 0; i < 8; i++)
#pragma unroll
        for (int j = 0; j < 4; j++) acc[i][j] = 0ULL;

    for (int kb = 0; kb < nkb; kb++) {
        if (kb + 1 < nkb) {
#pragma unroll
            for (int jj = 0; jj < 2; jj++) {
                int row = r0 + 64 * jj;
                pa[jj] = *(const float4*)(A + (size_t)(m0 + row) * K +
                                          (kb + 1) * 16 + c4 * 4);
                pb[jj] = *(const float4*)(Bbase + (size_t)row * K +
                                          (kb + 1) * 16 + c4 * 4);
            }
        }

        const float* As = Asf + (kb & 1) * TBUFF;
        const float* Bs = Bsf + (kb & 1) * TBUFF;

#pragma unroll
        for (int k = 0; k < 16; k++) {
            const float* ar = As + k * KSTR;
            const float* br = Bs + k * KSTR;
            float4 af0 = *(const float4*)(ar + 4 * ty);
            float4 af1 = *(const float4*)(ar + 64 + 4 * ty);
            ulonglong2 b0 = *(const ulonglong2*)(br + 4 * tx);
            ulonglong2 b1v = *(const ulonglong2*)(br + 64 + 4 * tx);
            ull av[8];
            av[0] = dup2(af0.x); av[1] = dup2(af0.y);
            av[2] = dup2(af0.z); av[3] = dup2(af0.w);
            av[4] = dup2(af1.x); av[5] = dup2(af1.y);
            av[6] = dup2(af1.z); av[7] = dup2(af1.w);
            ull bv[4] = {b0.x, b0.y, b1v.x, b1v.y};
#pragma unroll
            for (int i = 0; i < 8; i++)
#pragma unroll
                for (int j = 0; j < 4; j++)
                    fma2(acc[i][j], av[i], bv[j]);
        }

        if (kb + 1 < nkb) {
            int buf = (kb + 1) & 1;
            float av4[2][4] = {{pa[0].x, pa[0].y, pa[0].z, pa[0].w},
                               {pa[1].x, pa[1].y, pa[1].z, pa[1].w}};
            float bv4[2][4] = {{pb[0].x, pb[0].y, pb[0].z, pb[0].w},
                               {pb[1].x, pb[1].y, pb[1].z, pb[1].w}};
#pragma unroll
            for (int jj = 0; jj < 2; jj++) {
                int row = r0 + 64 * jj;
#pragma unroll
                for (int kk = 0; kk < 4; kk++) {
                    Asf[buf * TBUFF + (c4 * 4 + kk) * KSTR + row] = av4[jj][kk];
                    Bsf[buf * TBUFF + (c4 * 4 + kk) * KSTR + row] = bv4[jj][kk];
                }
            }
        }
        __syncthreads();
    }

    float bb[8];
#pragma unroll
    for (int q = 0; q < 8; q++) {
        int nc = (q < 4 ? 4 * tx + q : 64 + 4 * tx + (q - 4));
        bb[q] = bsel ? bsel[nrel + nc] : 0.0f;
    }
    const bool do_rope = (n0 < rope_cols);

#pragma unroll
    for (int i = 0; i < 8; i++) {
        int m = m0 + (i < 4 ? 4 * ty + i : 64 + 4 * ty + (i - 4));
        float* crow = C + (size_t)m * N + n0;
        float2 p0 = up2(acc[i][0]);
        float2 p1 = up2(acc[i][1]);
        float2 p2 = up2(acc[i][2]);
        float2 p3 = up2(acc[i][3]);
        float4 o0 = {p0.x + bb[0], p0.y + bb[1], p1.x + bb[2], p1.y + bb[3]};
        float4 o1 = {p2.x + bb[4], p2.y + bb[5], p3.x + bb[6], p3.y + bb[7]};
        if (do_rope) {
            float4 cs = *(const float4*)(g_cs + (size_t)m * 64 + 4 * tx);
            float4 sn = *(const float4*)(g_sn + (size_t)m * 64 + 4 * tx);
            float4 t0 = o0;
            o0.x = t0.x * cs.x - o1.x * sn.x;
            o0.y = t0.y * cs.y - o1.y * sn.y;
            o0.z = t0.z * cs.z - o1.z * sn.z;
            o0.w = t0.w * cs.w - o1.w * sn.w;
            o1.x = o1.x * cs.x + t0.x * sn.x;
            o1.y = o1.y * cs.y + t0.y * sn.y;
            o1.z = o1.z * cs.z + t0.z * sn.z;
            o1.w = o1.w * cs.w + t0.w * sn.w;
        }
        *(float4*)(crow + 4 * tx)      = o0;
        *(float4*)(crow + 64 + 4 * tx) = o1;
    }
}

// SPLITK-way partial reduction
__global__ void reduceK(float* __restrict__ out)
{
    int i = blockIdx.x * blockDim.x + threadIdx.x;
    const int n4 = S_LEN * HID / 4;
    if (i >= n4) return;
    const float4* p = (const float4*)g_P;
    float4 o = p[i];
#pragma unroll
    for (int z = 1; z < SPLITK; z++) {
        float4 v = p[(size_t)z * n4 + i];
        o.x += v.x; o.y += v.y; o.z += v.z; o.w += v.w;
    }
    ((float4*)out)[i] = o;
}

// ============================================================
// RoPE table
// ============================================================
__global__ void rope_table(const int* __restrict__ pos_ids)
{
    const int s = blockIdx.x;
    const int i = threadIdx.x;
    double inv = pow(10000.0, -(double)i / 64.0);
    double ang = (double)pos_ids[s] * inv;
    g_cs[s * 64 + i] = (float)cos(ang);
    g_sn[s * 64 + i] = (float)sin(ang);
}

// ============================================================
// Causal GQA flash-attention — f32x2, transposed-K (conflict-free),
// parallel softmax (4 thr/row), fast __expf.
// ============================================================
#define ATTN_SMEM_FLOATS (64*128 + 128*64 + 64*128 + 64*65 + 192)
#define ATTN_SMEM_BYTES  (ATTN_SMEM_FLOATS * 4)

__global__ void __launch_bounds__(256)
attn_kernel()
{
    extern __shared__ float sm[];
    float* Qs   = sm;
    float* Kst  = Qs  + 64 * 128;
    float* Vs   = Kst + 128 * 64;
    float* Ss   = Vs  + 64 * 128;
    float* mrow = Ss  + 64 * 65;
    float* lrow = mrow + 64;
    float* arow = lrow + 64;

    const int qt  = gridDim.x - 1 - blockIdx.x;
    const int h   = blockIdx.y;
    const int kvh = h / GROUPS;
    const int tid = threadIdx.x;
    const int qm  = qt * 64;
    const float scale = 0.08838834764831845f;

#pragma unroll
    for (int t = 0; t < 8; t++) {
        int idx = tid + 256 * t;
        int r   = idx >> 5;
        int c4  = idx & 31;
        float4 v = *(const float4*)(g_QKV + (size_t)(qm + r) * QKVW + h * HDIM + c4 * 4);
        v.x *= scale; v.y *= scale; v.z *= scale; v.w *= scale;
        *(float4*)(Qs + r * 128 + c4 * 4) = v;
    }

    ull acc2[16];
#pragma unroll
    for (int z = 0; z < 16; z++) acc2[z] = 0ULL;
    const int ocg  = tid >> 6;
    const int orow = tid & 63;

    if (tid < 64) { mrow[tid] = -1e30f; lrow[tid] = 0.0f; }
    __syncthreads();

    const int sx = tid & 15;
    const int sy = tid >> 4;
    const int ntiles = qt + 1;

    for (int kt = 0; kt < ntiles; kt++) {
        const int kn = kt * 64;
#pragma unroll
        for (int t = 0; t < 8; t++) {
            int idx = tid + 256 * t;
            int d4  = idx >> 6;
            int n   = idx & 63;
            float4 v = *(const float4*)(g_QKV + (size_t)(kn + n) * QKVW +
                                        HID + kvh * HDIM + d4 * 4);
            Kst[(d4 * 4 + 0) * 64 + n] = v.x;
            Kst[(d4 * 4 + 1) * 64 + n] = v.y;
            Kst[(d4 * 4 + 2) * 64 + n] = v.z;
            Kst[(d4 * 4 + 3) * 64 + n] = v.w;
        }
#pragma unroll
        for (int t = 0; t < 8; t++) {
            int idx = tid + 256 * t;
            int r   = idx >> 5;
            int c4  = idx & 31;
            *(float4*)(Vs + r * 128 + c4 * 4) =
                *(const float4*)(g_QKV + (size_t)(kn + r) * QKVW +
                                 HID + KVDIM + kvh * HDIM + c4 * 4);
        }
        __syncthreads();

        // ---- scores ----
        ull sacc2[4][2];
#pragma unroll
        for (int i = 0; i < 4; i++) { sacc2[i][0] = 0ULL; sacc2[i][1] = 0ULL; }

#pragma unroll 8
        for (int d = 0; d < 128; d += 4) {
            float4 av[4];
#pragma unroll
            for (int i = 0; i < 4; i++)
                av[i] = *(const float4*)(Qs + (sy * 4 + i) * 128 + d);
            ulonglong2 bp[4];
#pragma unroll
            for (int e = 0; e < 4; e++)
                bp[e] = *(const ulonglong2*)(Kst + (d + e) * 64 + sx * 4);
#pragma unroll
            for (int i = 0; i < 4; i++) {
                float ae[4] = {av[i].x, av[i].y, av[i].z, av[i].w};
#pragma unroll
                for (int e = 0; e < 4; e++) {
                    ull ad = dup2(ae[e]);
                    fma2(sacc2[i][0], ad, bp[e].x);
                    fma2(sacc2[i][1], ad, bp[e].y);
                }
            }
        }

        const bool diag = (kt == qt);
#pragma unroll
        for (int i = 0; i < 4; i++) {
            int qr = sy * 4 + i;
            float2 s0 = up2(sacc2[i][0]);
            float2 s1 = up2(sacc2[i][1]);
            float vj[4] = {s0.x, s0.y, s1.x, s1.y};
#pragma unroll
            for (int j = 0; j < 4; j++) {
                int kc = sx * 4 + j;
                float v = vj[j];
                if (diag && kc > qr) v = -1e30f;
                Ss[qr * 65 + kc] = v;
            }
        }
        __syncthreads();

        // ---- online softmax: 4 threads per row, fast exp ----
        {
            int r   = tid >> 2;
            int seg = tid & 3;
            float* sr = Ss + r * 65 + seg * 16;
            float mx = -1e30f;
#pragma unroll
            for (int k = 0; k < 16; k++) mx = fmaxf(mx, sr[k]);
            mx = fmaxf(mx, __shfl_xor_sync(0xffffffffu, mx, 1));
            mx = fmaxf(mx, __shfl_xor_sync(0xffffffffu, mx, 2));
            float m_old = mrow[r];
            float mnew  = fmaxf(m_old, mx);
            float sum = 0.0f;
#pragma unroll
            for (int k = 0; k < 16; k++) {
                float p = __expf(sr[k] - mnew);
                sr[k] = p;
                sum += p;
            }
            sum += __shfl_xor_sync(0xffffffffu, sum, 1);
            sum += __shfl_xor_sync(0xffffffffu, sum, 2);
            if (seg == 0) {
                float a = __expf(m_old - mnew);
                lrow[r] = lrow[r] * a + sum;
                mrow[r] = mnew;
                arow[r] = a;
            }
        }
        __syncthreads();

        // ---- rescale + PV ----
        {
            ull aa = dup2(arow[orow]);
#pragma unroll
            for (int z = 0; z < 16; z++) mul2(acc2[z], aa);
        }
        const float* srow = Ss + orow * 65;
#pragma unroll 4
        for (int kk = 0; kk < 64; kk++) {
            ull pp = dup2(srow[kk]);
            const float* vrow = Vs + kk * 128 + ocg * 32;
#pragma unroll
            for (int j = 0; j < 8; j++) {
                ulonglong2 v = *(const ulonglong2*)(vrow + j * 4);
                fma2(acc2[2 * j],     pp, v.x);
                fma2(acc2[2 * j + 1], pp, v.y);
            }
        }
        __syncthreads();
    }

    const float inv_l = 1.0f / lrow[orow];
    float* op = g_AO + (size_t)(qm + orow) * HID + h * HDIM + ocg * 32;
#pragma unroll
    for (int j = 0; j < 8; j++) {
        float2 e0 = up2(acc2[2 * j]);
        float2 e1 = up2(acc2[2 * j + 1]);
        float4 o = {e0.x * inv_l, e0.y * inv_l, e1.x * inv_l, e1.y * inv_l};
        *(float4*)(op + j * 4) = o;
    }
}

// ============================================================
// launch
// ============================================================
extern "C" void kernel_launch(void* const* d_in, const int* in_sizes, int n_in,
                              void* d_out, int out_size)
{
    const float* hs  = (const float*)d_in[0];
    const int*   pos = (const int*)  d_in[1];
    const float* Wq  = (const float*)d_in[2];
    const float* bq  = (const float*)d_in[3];
    const float* Wk  = (const float*)d_in[4];
    const float* bk  = (const float*)d_in[5];
    const float* Wv  = (const float*)d_in[6];
    const float* bv  = (const float*)d_in[7];
    const float* Wo  = (const float*)d_in[8];
    float* out = (float*)d_out;

    void *qkvp, *aop, *pp;
    cudaGetSymbolAddress(&qkvp, g_QKV);
    cudaGetSymbolAddress(&aop,  g_AO);
    cudaGetSymbolAddress(&pp,   g_P);

    cudaFuncSetAttribute(attn_kernel,
                         cudaFuncAttributeMaxDynamicSharedMemorySize,
                         ATTN_SMEM_BYTES);
    cudaFuncSetAttribute(gemm2,
                         cudaFuncAttributeMaxDynamicSharedMemorySize,
                         G2_SMEM);

    rope_table<<<S_LEN, 64>>>(pos);

    // fused QKV projection + RoPE epilogue (weights selected per n-block)
    gemm2<<<dim3(QKVW / 128, S_LEN / 128, 1), 256, G2_SMEM>>>(
        hs, Wq, Wk, Wv, bq, bk, bv, (float*)qkvp,
        QKVW, HID, ROPE_COLS, HID, HID + KVDIM);

    attn_kernel<<<dim3(S_LEN / 64, NHEADS), 256, ATTN_SMEM_BYTES>>>();

    // output projection: split-K into partials, then reduce
    gemm2<<<dim3(HID / 128, S_LEN / 128, SPLITK), 256, G2_SMEM>>>(
        (const float*)aop, Wo, Wo, Wo, nullptr, nullptr, nullptr,
        (float*)pp, HID, HID, 0, 1 << 30, 1 << 30);
    int n4 = S_LEN * HID / 4;
    reduceK<<<(n4 + 255) / 256, 256>>>(out);
}